// round 9
// baseline (speedup 1.0000x reference)
#include <cuda_runtime.h>
#include <math.h>

// TernaryTree1D: depth-8 ternary tree, BATCH=16384, 6561 leaves, 3280 internal nodes.
// R6: output layout locked (from out_size). R7: premultiplied packs, fast recip,
// branch-skipped clamp, 2 batch/thread (213->116.8us). R8: 4 batch/thread in stageA.

#define TT_BATCH 16384
#define TT_NLEAVES 6561
#define TT_NINTERNAL 3280
#define TT_EPS 1e-6f
#define TT_CAP 1000000.0f
#define TT_CAPSQ 1e12f

struct cfl { float re, im; };
__device__ __forceinline__ cfl mkc(float r, float i) { cfl v; v.re = r; v.im = i; return v; }

// ---- scratch (device globals, ~10.8 MB total — mem-guard-safe) ----
// leafPack: (w0*cr, w0*ci, w1, pad)
__device__ float4 d_leafPack[TT_NLEAVES];
// gatePack: 12 floats/node, 3 rows of (p_i0*c_ir, p_i0*c_ii, p_i1, p_i2)
__device__ float  d_gatePack[TT_NINTERNAL * 12];
__device__ float2 d_v81[81 * TT_BATCH];              // 81-level values, [j][b]

// ---------------------------------------------------------------------------
// prep: softmax leaf + gate logits; premultiplied packs; probs -> out.
// pstyle: 0 = no prob writes, 1 = packed float, 2 = complex (v, 0)
// ---------------------------------------------------------------------------
__global__ void prep_kernel(const float* __restrict__ leaf_logits,
                            const float* __restrict__ leaf_c,
                            const float* __restrict__ gate_logits,
                            const float* __restrict__ gate_c,
                            float* __restrict__ out,
                            int pstyle, int leafBase, int gateBase)
{
    int idx = blockIdx.x * blockDim.x + threadIdx.x;

    if (idx < TT_NLEAVES) {
        float l0 = leaf_logits[idx * 2 + 0];
        float l1 = leaf_logits[idx * 2 + 1];
        float m  = fmaxf(l0, l1);
        float e0 = expf(l0 - m), e1 = expf(l1 - m);
        float s  = e0 + e1;
        float w0 = e0 / s, w1 = e1 / s;
        if (pstyle == 1) {
            out[leafBase + idx * 2 + 0] = w0;
            out[leafBase + idx * 2 + 1] = w1;
        } else if (pstyle == 2) {
            out[leafBase + idx * 4 + 0] = w0; out[leafBase + idx * 4 + 1] = 0.0f;
            out[leafBase + idx * 4 + 2] = w1; out[leafBase + idx * 4 + 3] = 0.0f;
        }
        float cr = leaf_c[idx * 2 + 0];
        float ci = leaf_c[idx * 2 + 1];
        d_leafPack[idx] = make_float4(w0 * cr, w0 * ci, w1, 0.0f);
    }

    if (idx < TT_NINTERNAL * 3) {
        int n = idx / 3;
        int i = idx % 3;
        float g0 = gate_logits[n * 9 + i * 3 + 0];
        float g1 = gate_logits[n * 9 + i * 3 + 1];
        float g2 = gate_logits[n * 9 + i * 3 + 2];
        float m  = fmaxf(g0, fmaxf(g1, g2));
        float e0 = expf(g0 - m), e1 = expf(g1 - m), e2 = expf(g2 - m);
        float s  = e0 + e1 + e2;
        float p0 = e0 / s, p1 = e1 / s, p2 = e2 / s;
        int k = n * 9 + i * 3;
        if (pstyle == 1) {
            out[gateBase + k + 0] = p0;
            out[gateBase + k + 1] = p1;
            out[gateBase + k + 2] = p2;
        } else if (pstyle == 2) {
            int base = gateBase + 2 * k;
            out[base + 0] = p0; out[base + 1] = 0.0f;
            out[base + 2] = p1; out[base + 3] = 0.0f;
            out[base + 4] = p2; out[base + 5] = 0.0f;
        }
        float cr = gate_c[n * 6 + i * 2 + 0];
        float ci = gate_c[n * 6 + i * 2 + 1];
        float* g = d_gatePack + n * 12 + i * 4;
        g[0] = p0 * cr;   // e
        g[1] = p0 * ci;   // f
        g[2] = p1;        // x coeff
        g[3] = p2;        // child coeff
    }
}

// ---------------------------------------------------------------------------
// node over U independent batch elements sharing constants.
// row pack: (e, f, p1, p2): in = (e + p1*x + p2*ch.re, f + p2*ch.im)
// Clamp scale is exactly 1.0 when |out| <= CAP => sqrt/div only on rare path.
// ---------------------------------------------------------------------------
template<int U>
__device__ __forceinline__ void nodeU(const float* __restrict__ gp,
                                      const float* __restrict__ xr,
                                      const cfl* va, const cfl* vb, const cfl* vc,
                                      cfl* o)
{
    const float4* g4 = reinterpret_cast<const float4*>(gp);
    float4 r0 = __ldg(g4 + 0);
    float4 r1 = __ldg(g4 + 1);
    float4 r2 = __ldg(g4 + 2);
#pragma unroll
    for (int u = 0; u < U; ++u) {
        float ar = r0.x + r0.z * xr[u] + r0.w * va[u].re;
        float ai = r0.y + r0.w * va[u].im;
        float br = r1.x + r1.z * xr[u] + r1.w * vb[u].re;
        float bi = r1.y + r1.w * vb[u].im;
        float cr = r2.x + r2.z * xr[u] + r2.w * vc[u].re;
        float ci = r2.y + r2.w * vc[u].im;

        float den = cr * cr + ci * ci + TT_EPS;
        float abr = ar * br - ai * bi;
        float abi = ar * bi + ai * br;
        float nr  = abr * cr + abi * ci;     // (a*b)*conj(c)
        float ni  = abi * cr - abr * ci;
        float inv = __fdividef(1.0f, den);
        float orr = nr * inv;
        float oi  = ni * inv;
        float m2  = orr * orr + oi * oi;
        if (m2 > TT_CAPSQ) {                 // rare: actually clamped
            float s = TT_CAP / sqrtf(m2);
            orr *= s; oi *= s;
        }
        o[u] = mkc(orr, oi);
    }
}

// ---------------------------------------------------------------------------
// stage A: each thread folds one depth-4 subtree for U batch elements.
// gate bases: 2187-level @0, 729-level @2187, 243-level @2916, 81-level @3159
// ---------------------------------------------------------------------------
template<int U>
__global__ void __launch_bounds__(256) stageA_kernel(const float* __restrict__ x)
{
    constexpr int STRIDE = TT_BATCH / U;
    int b0 = blockIdx.x * blockDim.x + threadIdx.x;   // 0..STRIDE-1
    int j  = blockIdx.y;                               // subtree 0..80
    float xr[U];
#pragma unroll
    for (int u = 0; u < U; ++u) xr[u] = __ldg(&x[b0 + u * STRIDE]);

    int leafBase  = j * 81;
    int g2187Base = j * 27;
    int g729Base  = 2187 + j * 9;
    int g243Base  = 2916 + j * 3;

    cfl A3[U], B3[U], C3[U];
#pragma unroll
    for (int u = 0; u < U; ++u) { A3[u] = mkc(0,0); B3[u] = mkc(0,0); C3[u] = mkc(0,0); }

#pragma unroll 1
    for (int i3 = 0; i3 < 3; ++i3) {
        cfl A2[U], B2[U], C2[U];
#pragma unroll
        for (int i2 = 0; i2 < 3; ++i2) {
            cfl v1[3][U];
#pragma unroll
            for (int i1 = 0; i1 < 3; ++i1) {
                cfl lv[3][U];
#pragma unroll
                for (int i0 = 0; i0 < 3; ++i0) {
                    int l = leafBase + ((i3 * 3 + i2) * 3 + i1) * 3 + i0;
                    float4 lp = __ldg(&d_leafPack[l]);
#pragma unroll
                    for (int u = 0; u < U; ++u)
                        lv[i0][u] = mkc(lp.x + lp.z * xr[u], lp.y);
                }
                int g = g2187Base + (i3 * 3 + i2) * 3 + i1;
                nodeU<U>(d_gatePack + g * 12, xr, lv[0], lv[1], lv[2], v1[i1]);
            }
            cfl v2[U];
            nodeU<U>(d_gatePack + (g729Base + i3 * 3 + i2) * 12, xr,
                     v1[0], v1[1], v1[2], v2);
#pragma unroll
            for (int u = 0; u < U; ++u) {
                if (i2 == 0) A2[u] = v2[u];
                else if (i2 == 1) B2[u] = v2[u];
                else C2[u] = v2[u];
            }
        }
        cfl v3[U];
        nodeU<U>(d_gatePack + (g243Base + i3) * 12, xr, A2, B2, C2, v3);
#pragma unroll
        for (int u = 0; u < U; ++u) { A3[u] = B3[u]; B3[u] = C3[u]; C3[u] = v3[u]; }
    }
    cfl v[U];
    nodeU<U>(d_gatePack + (3159 + j) * 12, xr, A3, B3, C3, v);
#pragma unroll
    for (int u = 0; u < U; ++u)
        d_v81[j * TT_BATCH + b0 + u * STRIDE] = make_float2(v[u].re, v[u].im);
}

// ---------------------------------------------------------------------------
// stage B: fold 81 -> 1; gate bases 27@3240, 9@3267, 3@3276, root@3279
// rmode: 0 = interleaved (re,im); 1 = planar re then im; 2 = re only
// ---------------------------------------------------------------------------
__global__ void __launch_bounds__(256) stageB_kernel(const float* __restrict__ x,
                                                     float* __restrict__ out,
                                                     int rmode)
{
    int b = blockIdx.x * blockDim.x + threadIdx.x;
    float xr[1];
    xr[0] = __ldg(&x[b]);

    cfl A3[1], B3[1], C3[1];
    A3[0] = mkc(0,0); B3[0] = mkc(0,0); C3[0] = mkc(0,0);

#pragma unroll 1
    for (int i3 = 0; i3 < 3; ++i3) {
        cfl A2[1], B2[1], C2[1];
#pragma unroll
        for (int i2 = 0; i2 < 3; ++i2) {
            cfl v1[3][1];
#pragma unroll
            for (int i1 = 0; i1 < 3; ++i1) {
                int m = (i3 * 3 + i2) * 3 + i1;   // 27-level node 0..26
                float2 u0 = __ldg(&d_v81[(3 * m + 0) * TT_BATCH + b]);
                float2 u1 = __ldg(&d_v81[(3 * m + 1) * TT_BATCH + b]);
                float2 u2 = __ldg(&d_v81[(3 * m + 2) * TT_BATCH + b]);
                cfl c0[1] = { mkc(u0.x, u0.y) };
                cfl c1[1] = { mkc(u1.x, u1.y) };
                cfl c2[1] = { mkc(u2.x, u2.y) };
                nodeU<1>(d_gatePack + (3240 + m) * 12, xr, c0, c1, c2, v1[i1]);
            }
            cfl v2[1];
            nodeU<1>(d_gatePack + (3267 + i3 * 3 + i2) * 12, xr,
                     v1[0], v1[1], v1[2], v2);
            if (i2 == 0) A2[0] = v2[0]; else if (i2 == 1) B2[0] = v2[0]; else C2[0] = v2[0];
        }
        cfl v3[1];
        nodeU<1>(d_gatePack + (3276 + i3) * 12, xr, A2, B2, C2, v3);
        A3[0] = B3[0]; B3[0] = C3[0]; C3[0] = v3[0];
    }
    cfl r[1];
    nodeU<1>(d_gatePack + 3279 * 12, xr, A3, B3, C3, r);

    if (rmode == 0) {
        out[2 * b + 0] = r[0].re;
        out[2 * b + 1] = r[0].im;
    } else if (rmode == 1) {
        out[b]            = r[0].re;
        out[TT_BATCH + b] = r[0].im;
    } else {
        out[b] = r[0].re;
    }
}

// ---------------------------------------------------------------------------
extern "C" void kernel_launch(void* const* d_in, const int* in_sizes, int n_in,
                              void* d_out, int out_size)
{
    // size-based input resolution (dict order; first 13122 = leaf_logits)
    const float* x  = 0;
    const float* ll = 0;
    const float* lc = 0;
    const float* gl = 0;
    const float* gc = 0;
    int n13122 = 0;
    for (int i = 0; i < n_in; ++i) {
        const float* p = (const float*)d_in[i];
        int s = in_sizes[i];
        if      (s == 16384) x  = p;
        else if (s == 29520) gl = p;
        else if (s == 19680) gc = p;
        else if (s == 13122) { if (n13122++ == 0) ll = p; else lc = p; }
    }
    float* out = (float*)d_out;

    // ---- output layout selection from out_size (VALIDATED in R6 — do not change) ----
    int pstyle, leafBase, gateBase, rmode;
    if (out_size == 59026) {
        rmode = 2; pstyle = 1; leafBase = 16384; gateBase = 29506;   // real-part concat
    } else if (out_size == 75410) {
        rmode = 1; pstyle = 1; leafBase = 32768; gateBase = 45890;   // planar + float probs
    } else if (out_size == 118052) {
        rmode = 0; pstyle = 2; leafBase = 32768; gateBase = 32768 + 26244;
    } else if (out_size == 32768) {
        rmode = 1; pstyle = 0; leafBase = 0; gateBase = 0;
    } else if (out_size == 16384) {
        rmode = 2; pstyle = 0; leafBase = 0; gateBase = 0;
    } else {
        rmode = 0; pstyle = 0; leafBase = 0; gateBase = 0;
    }

    int prepThreads = TT_NINTERNAL * 3;
    prep_kernel<<<(prepThreads + 255) / 256, 256>>>(ll, lc, gl, gc, out,
                                                    pstyle, leafBase, gateBase);

    constexpr int U = 4;                       // 4 batch elements per stageA thread
    dim3 gridA((TT_BATCH / U) / 256, 81);      // (16, 81)
    stageA_kernel<U><<<gridA, 256>>>(x);

    stageB_kernel<<<TT_BATCH / 256, 256>>>(x, out, rmode);
}

// round 11
// speedup vs baseline: 1.4451x; 1.4451x over previous
#include <cuda_runtime.h>
#include <math.h>

// TernaryTree1D: depth-8 ternary tree, BATCH=16384, 6561 leaves, 3280 internal nodes.
// R6: output layout locked. R7: premultiplied packs, fast recip, U=2 (116.8us).
// R8: U=4 regressed (reg pressure) -> reverted. R9: branchless clamp (no BSSY) +
// shared-memory staged constants in stageA.

#define TT_BATCH 16384
#define TT_HALFB 8192
#define TT_NLEAVES 6561
#define TT_NINTERNAL 3280
#define TT_EPS 1e-6f
#define TT_CAP 1000000.0f

struct cfl { float re, im; };
__device__ __forceinline__ cfl mkc(float r, float i) { cfl v; v.re = r; v.im = i; return v; }

// ---- scratch (device globals, ~10.8 MB total — mem-guard-safe) ----
__device__ float4 d_leafPack[TT_NLEAVES];            // (w0*cr, w0*ci, w1, pad)
__device__ float  d_gatePack[TT_NINTERNAL * 12];     // 3 rows of (p0*cr, p0*ci, p1, p2)
__device__ float2 d_v81[81 * TT_BATCH];              // 81-level values, [j][b]

// ---------------------------------------------------------------------------
// prep: softmax leaf + gate logits; premultiplied packs; probs -> out.
// ---------------------------------------------------------------------------
__global__ void prep_kernel(const float* __restrict__ leaf_logits,
                            const float* __restrict__ leaf_c,
                            const float* __restrict__ gate_logits,
                            const float* __restrict__ gate_c,
                            float* __restrict__ out,
                            int pstyle, int leafBase, int gateBase)
{
    int idx = blockIdx.x * blockDim.x + threadIdx.x;

    if (idx < TT_NLEAVES) {
        float l0 = leaf_logits[idx * 2 + 0];
        float l1 = leaf_logits[idx * 2 + 1];
        float m  = fmaxf(l0, l1);
        float e0 = expf(l0 - m), e1 = expf(l1 - m);
        float s  = e0 + e1;
        float w0 = e0 / s, w1 = e1 / s;
        if (pstyle == 1) {
            out[leafBase + idx * 2 + 0] = w0;
            out[leafBase + idx * 2 + 1] = w1;
        } else if (pstyle == 2) {
            out[leafBase + idx * 4 + 0] = w0; out[leafBase + idx * 4 + 1] = 0.0f;
            out[leafBase + idx * 4 + 2] = w1; out[leafBase + idx * 4 + 3] = 0.0f;
        }
        float cr = leaf_c[idx * 2 + 0];
        float ci = leaf_c[idx * 2 + 1];
        d_leafPack[idx] = make_float4(w0 * cr, w0 * ci, w1, 0.0f);
    }

    if (idx < TT_NINTERNAL * 3) {
        int n = idx / 3;
        int i = idx % 3;
        float g0 = gate_logits[n * 9 + i * 3 + 0];
        float g1 = gate_logits[n * 9 + i * 3 + 1];
        float g2 = gate_logits[n * 9 + i * 3 + 2];
        float m  = fmaxf(g0, fmaxf(g1, g2));
        float e0 = expf(g0 - m), e1 = expf(g1 - m), e2 = expf(g2 - m);
        float s  = e0 + e1 + e2;
        float p0 = e0 / s, p1 = e1 / s, p2 = e2 / s;
        int k = n * 9 + i * 3;
        if (pstyle == 1) {
            out[gateBase + k + 0] = p0;
            out[gateBase + k + 1] = p1;
            out[gateBase + k + 2] = p2;
        } else if (pstyle == 2) {
            int base = gateBase + 2 * k;
            out[base + 0] = p0; out[base + 1] = 0.0f;
            out[base + 2] = p1; out[base + 3] = 0.0f;
            out[base + 4] = p2; out[base + 5] = 0.0f;
        }
        float cr = gate_c[n * 6 + i * 2 + 0];
        float ci = gate_c[n * 6 + i * 2 + 1];
        float* g = d_gatePack + n * 12 + i * 4;
        g[0] = p0 * cr;
        g[1] = p0 * ci;
        g[2] = p1;
        g[3] = p2;
    }
}

// ---------------------------------------------------------------------------
// branchless node body. Clamp: s = min(1, CAP*rsqrt(|o|^2)); exactly 1.0 when
// |o| <= CAP (matches reference CAP/CAP), ~1-ulp rsqrt on the rare clamped path.
// ---------------------------------------------------------------------------
template<int U>
__device__ __forceinline__ void node_core(float4 r0, float4 r1, float4 r2,
                                          const float* __restrict__ xr,
                                          const cfl* va, const cfl* vb, const cfl* vc,
                                          cfl* o)
{
#pragma unroll
    for (int u = 0; u < U; ++u) {
        float ar = r0.x + r0.z * xr[u] + r0.w * va[u].re;
        float ai = r0.y + r0.w * va[u].im;
        float br = r1.x + r1.z * xr[u] + r1.w * vb[u].re;
        float bi = r1.y + r1.w * vb[u].im;
        float cr = r2.x + r2.z * xr[u] + r2.w * vc[u].re;
        float ci = r2.y + r2.w * vc[u].im;

        float den = cr * cr + ci * ci + TT_EPS;
        float abr = ar * br - ai * bi;
        float abi = ar * bi + ai * br;
        float nr  = abr * cr + abi * ci;     // (a*b)*conj(c)
        float ni  = abi * cr - abr * ci;
        float inv = __fdividef(1.0f, den);
        float orr = nr * inv;
        float oi  = ni * inv;
        float m2  = orr * orr + oi * oi;
        float s   = fminf(1.0f, TT_CAP * rsqrtf(m2));   // branchless clamp
        o[u] = mkc(orr * s, oi * s);
    }
}

// global-memory constant variant (stageB)
template<int U>
__device__ __forceinline__ void nodeG(const float* __restrict__ gp,
                                      const float* __restrict__ xr,
                                      const cfl* va, const cfl* vb, const cfl* vc,
                                      cfl* o)
{
    const float4* g4 = reinterpret_cast<const float4*>(gp);
    node_core<U>(__ldg(g4 + 0), __ldg(g4 + 1), __ldg(g4 + 2), xr, va, vb, vc, o);
}

// shared-memory constant variant (stageA)
template<int U>
__device__ __forceinline__ void nodeS(const float* gp,
                                      const float* __restrict__ xr,
                                      const cfl* va, const cfl* vb, const cfl* vc,
                                      cfl* o)
{
    const float4* g4 = reinterpret_cast<const float4*>(gp);
    node_core<U>(g4[0], g4[1], g4[2], xr, va, vb, vc, o);
}

// ---------------------------------------------------------------------------
// stage A: thread folds one depth-4 subtree for 2 batch elements.
// Block-local constants staged in shared memory:
//   sG[0..27)*12  : 2187-level gates (base j*27)
//   sG[27..36)*12 : 729-level gates  (base 2187 + j*9)
//   sG[36..39)*12 : 243-level gates  (base 2916 + j*3)
//   sG[39]*12     : 81-level gate    (3159 + j)
// ---------------------------------------------------------------------------
__global__ void __launch_bounds__(256) stageA_kernel(const float* __restrict__ x)
{
    __shared__ __align__(16) float  sG[40 * 12];
    __shared__ __align__(16) float4 sL[81];

    int j = blockIdx.y;                               // subtree 0..80
    int t = threadIdx.x;

    int leafBase  = j * 81;
    int g2187Base = j * 27;
    int g729Base  = 2187 + j * 9;
    int g243Base  = 2916 + j * 3;

    // cooperative preload of block constants
    for (int q = t; q < 40 * 12; q += 256) {
        int lg = q / 12, r = q - lg * 12;
        int gg = (lg < 27) ? (g2187Base + lg)
               : (lg < 36) ? (g729Base + (lg - 27))
               : (lg < 39) ? (g243Base + (lg - 36))
                           : (3159 + j);
        sG[q] = d_gatePack[gg * 12 + r];
    }
    for (int q = t; q < 81; q += 256)
        sL[q] = d_leafPack[leafBase + q];
    __syncthreads();

    int b0 = blockIdx.x * blockDim.x + t;             // 0..8191
    float xr[2];
    xr[0] = __ldg(&x[b0]);
    xr[1] = __ldg(&x[b0 + TT_HALFB]);

    cfl A3[2], B3[2], C3[2];
#pragma unroll
    for (int u = 0; u < 2; ++u) { A3[u] = mkc(0,0); B3[u] = mkc(0,0); C3[u] = mkc(0,0); }

#pragma unroll 1
    for (int i3 = 0; i3 < 3; ++i3) {
        cfl A2[2], B2[2], C2[2];
#pragma unroll
        for (int i2 = 0; i2 < 3; ++i2) {
            cfl v1[3][2];
#pragma unroll
            for (int i1 = 0; i1 < 3; ++i1) {
                cfl lv[3][2];
#pragma unroll
                for (int i0 = 0; i0 < 3; ++i0) {
                    int l = ((i3 * 3 + i2) * 3 + i1) * 3 + i0;   // 0..80 local
                    float4 lp = sL[l];
#pragma unroll
                    for (int u = 0; u < 2; ++u)
                        lv[i0][u] = mkc(lp.x + lp.z * xr[u], lp.y);
                }
                int g = (i3 * 3 + i2) * 3 + i1;                  // local 0..26
                nodeS<2>(sG + g * 12, xr, lv[0], lv[1], lv[2], v1[i1]);
            }
            cfl v2[2];
            nodeS<2>(sG + (27 + i3 * 3 + i2) * 12, xr, v1[0], v1[1], v1[2], v2);
#pragma unroll
            for (int u = 0; u < 2; ++u) {
                if (i2 == 0) A2[u] = v2[u];
                else if (i2 == 1) B2[u] = v2[u];
                else C2[u] = v2[u];
            }
        }
        cfl v3[2];
        nodeS<2>(sG + (36 + i3) * 12, xr, A2, B2, C2, v3);
#pragma unroll
        for (int u = 0; u < 2; ++u) { A3[u] = B3[u]; B3[u] = C3[u]; C3[u] = v3[u]; }
    }
    cfl v[2];
    nodeS<2>(sG + 39 * 12, xr, A3, B3, C3, v);
    d_v81[j * TT_BATCH + b0]            = make_float2(v[0].re, v[0].im);
    d_v81[j * TT_BATCH + b0 + TT_HALFB] = make_float2(v[1].re, v[1].im);
}

// ---------------------------------------------------------------------------
// stage B: fold 81 -> 1; gate bases 27@3240, 9@3267, 3@3276, root@3279
// rmode: 0 = interleaved (re,im); 1 = planar re then im; 2 = re only
// ---------------------------------------------------------------------------
__global__ void __launch_bounds__(256) stageB_kernel(const float* __restrict__ x,
                                                     float* __restrict__ out,
                                                     int rmode)
{
    int b = blockIdx.x * blockDim.x + threadIdx.x;
    float xr[1];
    xr[0] = __ldg(&x[b]);

    cfl A3[1], B3[1], C3[1];
    A3[0] = mkc(0,0); B3[0] = mkc(0,0); C3[0] = mkc(0,0);

#pragma unroll 1
    for (int i3 = 0; i3 < 3; ++i3) {
        cfl A2[1], B2[1], C2[1];
#pragma unroll
        for (int i2 = 0; i2 < 3; ++i2) {
            cfl v1[3][1];
#pragma unroll
            for (int i1 = 0; i1 < 3; ++i1) {
                int m = (i3 * 3 + i2) * 3 + i1;   // 27-level node 0..26
                float2 u0 = __ldg(&d_v81[(3 * m + 0) * TT_BATCH + b]);
                float2 u1 = __ldg(&d_v81[(3 * m + 1) * TT_BATCH + b]);
                float2 u2 = __ldg(&d_v81[(3 * m + 2) * TT_BATCH + b]);
                cfl c0[1] = { mkc(u0.x, u0.y) };
                cfl c1[1] = { mkc(u1.x, u1.y) };
                cfl c2[1] = { mkc(u2.x, u2.y) };
                nodeG<1>(d_gatePack + (3240 + m) * 12, xr, c0, c1, c2, v1[i1]);
            }
            cfl v2[1];
            nodeG<1>(d_gatePack + (3267 + i3 * 3 + i2) * 12, xr,
                     v1[0], v1[1], v1[2], v2);
            if (i2 == 0) A2[0] = v2[0]; else if (i2 == 1) B2[0] = v2[0]; else C2[0] = v2[0];
        }
        cfl v3[1];
        nodeG<1>(d_gatePack + (3276 + i3) * 12, xr, A2, B2, C2, v3);
        A3[0] = B3[0]; B3[0] = C3[0]; C3[0] = v3[0];
    }
    cfl r[1];
    nodeG<1>(d_gatePack + 3279 * 12, xr, A3, B3, C3, r);

    if (rmode == 0) {
        out[2 * b + 0] = r[0].re;
        out[2 * b + 1] = r[0].im;
    } else if (rmode == 1) {
        out[b]            = r[0].re;
        out[TT_BATCH + b] = r[0].im;
    } else {
        out[b] = r[0].re;
    }
}

// ---------------------------------------------------------------------------
extern "C" void kernel_launch(void* const* d_in, const int* in_sizes, int n_in,
                              void* d_out, int out_size)
{
    // size-based input resolution (dict order; first 13122 = leaf_logits)
    const float* x  = 0;
    const float* ll = 0;
    const float* lc = 0;
    const float* gl = 0;
    const float* gc = 0;
    int n13122 = 0;
    for (int i = 0; i < n_in; ++i) {
        const float* p = (const float*)d_in[i];
        int s = in_sizes[i];
        if      (s == 16384) x  = p;
        else if (s == 29520) gl = p;
        else if (s == 19680) gc = p;
        else if (s == 13122) { if (n13122++ == 0) ll = p; else lc = p; }
    }
    float* out = (float*)d_out;

    // ---- output layout selection from out_size (VALIDATED in R6 — do not change) ----
    int pstyle, leafBase, gateBase, rmode;
    if (out_size == 59026) {
        rmode = 2; pstyle = 1; leafBase = 16384; gateBase = 29506;   // real-part concat
    } else if (out_size == 75410) {
        rmode = 1; pstyle = 1; leafBase = 32768; gateBase = 45890;
    } else if (out_size == 118052) {
        rmode = 0; pstyle = 2; leafBase = 32768; gateBase = 32768 + 26244;
    } else if (out_size == 32768) {
        rmode = 1; pstyle = 0; leafBase = 0; gateBase = 0;
    } else if (out_size == 16384) {
        rmode = 2; pstyle = 0; leafBase = 0; gateBase = 0;
    } else {
        rmode = 0; pstyle = 0; leafBase = 0; gateBase = 0;
    }

    int prepThreads = TT_NINTERNAL * 3;
    prep_kernel<<<(prepThreads + 255) / 256, 256>>>(ll, lc, gl, gc, out,
                                                    pstyle, leafBase, gateBase);

    dim3 gridA(TT_HALFB / 256, 81);      // U=2 batch elements per thread
    stageA_kernel<<<gridA, 256>>>(x);

    stageB_kernel<<<TT_BATCH / 256, 256>>>(x, out, rmode);
}

// round 12
// speedup vs baseline: 1.4465x; 1.0010x over previous
#include <cuda_runtime.h>
#include <math.h>

// TernaryTree1D: depth-8 ternary tree, BATCH=16384, 6561 leaves, 3280 internal nodes.
// R6: output layout locked. R7: premultiplied packs, fast recip, U=2 (116.8us).
// R8: U=4 regressed (reg pressure) -> reverted. R9: branchless clamp (no BSSY) +
// shared-memory staged constants in stageA.

#define TT_BATCH 16384
#define TT_HALFB 8192
#define TT_NLEAVES 6561
#define TT_NINTERNAL 3280
#define TT_EPS 1e-6f
#define TT_CAP 1000000.0f

struct cfl { float re, im; };
__device__ __forceinline__ cfl mkc(float r, float i) { cfl v; v.re = r; v.im = i; return v; }

// ---- scratch (device globals, ~10.8 MB total — mem-guard-safe) ----
__device__ float4 d_leafPack[TT_NLEAVES];            // (w0*cr, w0*ci, w1, pad)
__device__ float  d_gatePack[TT_NINTERNAL * 12];     // 3 rows of (p0*cr, p0*ci, p1, p2)
__device__ float2 d_v81[81 * TT_BATCH];              // 81-level values, [j][b]

// ---------------------------------------------------------------------------
// prep: softmax leaf + gate logits; premultiplied packs; probs -> out.
// ---------------------------------------------------------------------------
__global__ void prep_kernel(const float* __restrict__ leaf_logits,
                            const float* __restrict__ leaf_c,
                            const float* __restrict__ gate_logits,
                            const float* __restrict__ gate_c,
                            float* __restrict__ out,
                            int pstyle, int leafBase, int gateBase)
{
    int idx = blockIdx.x * blockDim.x + threadIdx.x;

    if (idx < TT_NLEAVES) {
        float l0 = leaf_logits[idx * 2 + 0];
        float l1 = leaf_logits[idx * 2 + 1];
        float m  = fmaxf(l0, l1);
        float e0 = expf(l0 - m), e1 = expf(l1 - m);
        float s  = e0 + e1;
        float w0 = e0 / s, w1 = e1 / s;
        if (pstyle == 1) {
            out[leafBase + idx * 2 + 0] = w0;
            out[leafBase + idx * 2 + 1] = w1;
        } else if (pstyle == 2) {
            out[leafBase + idx * 4 + 0] = w0; out[leafBase + idx * 4 + 1] = 0.0f;
            out[leafBase + idx * 4 + 2] = w1; out[leafBase + idx * 4 + 3] = 0.0f;
        }
        float cr = leaf_c[idx * 2 + 0];
        float ci = leaf_c[idx * 2 + 1];
        d_leafPack[idx] = make_float4(w0 * cr, w0 * ci, w1, 0.0f);
    }

    if (idx < TT_NINTERNAL * 3) {
        int n = idx / 3;
        int i = idx % 3;
        float g0 = gate_logits[n * 9 + i * 3 + 0];
        float g1 = gate_logits[n * 9 + i * 3 + 1];
        float g2 = gate_logits[n * 9 + i * 3 + 2];
        float m  = fmaxf(g0, fmaxf(g1, g2));
        float e0 = expf(g0 - m), e1 = expf(g1 - m), e2 = expf(g2 - m);
        float s  = e0 + e1 + e2;
        float p0 = e0 / s, p1 = e1 / s, p2 = e2 / s;
        int k = n * 9 + i * 3;
        if (pstyle == 1) {
            out[gateBase + k + 0] = p0;
            out[gateBase + k + 1] = p1;
            out[gateBase + k + 2] = p2;
        } else if (pstyle == 2) {
            int base = gateBase + 2 * k;
            out[base + 0] = p0; out[base + 1] = 0.0f;
            out[base + 2] = p1; out[base + 3] = 0.0f;
            out[base + 4] = p2; out[base + 5] = 0.0f;
        }
        float cr = gate_c[n * 6 + i * 2 + 0];
        float ci = gate_c[n * 6 + i * 2 + 1];
        float* g = d_gatePack + n * 12 + i * 4;
        g[0] = p0 * cr;
        g[1] = p0 * ci;
        g[2] = p1;
        g[3] = p2;
    }
}

// ---------------------------------------------------------------------------
// branchless node body. Clamp: s = min(1, CAP*rsqrt(|o|^2)); exactly 1.0 when
// |o| <= CAP (matches reference CAP/CAP), ~1-ulp rsqrt on the rare clamped path.
// ---------------------------------------------------------------------------
template<int U>
__device__ __forceinline__ void node_core(float4 r0, float4 r1, float4 r2,
                                          const float* __restrict__ xr,
                                          const cfl* va, const cfl* vb, const cfl* vc,
                                          cfl* o)
{
#pragma unroll
    for (int u = 0; u < U; ++u) {
        float ar = r0.x + r0.z * xr[u] + r0.w * va[u].re;
        float ai = r0.y + r0.w * va[u].im;
        float br = r1.x + r1.z * xr[u] + r1.w * vb[u].re;
        float bi = r1.y + r1.w * vb[u].im;
        float cr = r2.x + r2.z * xr[u] + r2.w * vc[u].re;
        float ci = r2.y + r2.w * vc[u].im;

        float den = cr * cr + ci * ci + TT_EPS;
        float abr = ar * br - ai * bi;
        float abi = ar * bi + ai * br;
        float nr  = abr * cr + abi * ci;     // (a*b)*conj(c)
        float ni  = abi * cr - abr * ci;
        float inv = __fdividef(1.0f, den);
        float orr = nr * inv;
        float oi  = ni * inv;
        float m2  = orr * orr + oi * oi;
        float s   = fminf(1.0f, TT_CAP * rsqrtf(m2));   // branchless clamp
        o[u] = mkc(orr * s, oi * s);
    }
}

// global-memory constant variant (stageB)
template<int U>
__device__ __forceinline__ void nodeG(const float* __restrict__ gp,
                                      const float* __restrict__ xr,
                                      const cfl* va, const cfl* vb, const cfl* vc,
                                      cfl* o)
{
    const float4* g4 = reinterpret_cast<const float4*>(gp);
    node_core<U>(__ldg(g4 + 0), __ldg(g4 + 1), __ldg(g4 + 2), xr, va, vb, vc, o);
}

// shared-memory constant variant (stageA)
template<int U>
__device__ __forceinline__ void nodeS(const float* gp,
                                      const float* __restrict__ xr,
                                      const cfl* va, const cfl* vb, const cfl* vc,
                                      cfl* o)
{
    const float4* g4 = reinterpret_cast<const float4*>(gp);
    node_core<U>(g4[0], g4[1], g4[2], xr, va, vb, vc, o);
}

// ---------------------------------------------------------------------------
// stage A: thread folds one depth-4 subtree for 2 batch elements.
// Block-local constants staged in shared memory:
//   sG[0..27)*12  : 2187-level gates (base j*27)
//   sG[27..36)*12 : 729-level gates  (base 2187 + j*9)
//   sG[36..39)*12 : 243-level gates  (base 2916 + j*3)
//   sG[39]*12     : 81-level gate    (3159 + j)
// ---------------------------------------------------------------------------
__global__ void __launch_bounds__(256) stageA_kernel(const float* __restrict__ x)
{
    __shared__ __align__(16) float  sG[40 * 12];
    __shared__ __align__(16) float4 sL[81];

    int j = blockIdx.y;                               // subtree 0..80
    int t = threadIdx.x;

    int leafBase  = j * 81;
    int g2187Base = j * 27;
    int g729Base  = 2187 + j * 9;
    int g243Base  = 2916 + j * 3;

    // cooperative preload of block constants
    for (int q = t; q < 40 * 12; q += 256) {
        int lg = q / 12, r = q - lg * 12;
        int gg = (lg < 27) ? (g2187Base + lg)
               : (lg < 36) ? (g729Base + (lg - 27))
               : (lg < 39) ? (g243Base + (lg - 36))
                           : (3159 + j);
        sG[q] = d_gatePack[gg * 12 + r];
    }
    for (int q = t; q < 81; q += 256)
        sL[q] = d_leafPack[leafBase + q];
    __syncthreads();

    int b0 = blockIdx.x * blockDim.x + t;             // 0..8191
    float xr[2];
    xr[0] = __ldg(&x[b0]);
    xr[1] = __ldg(&x[b0 + TT_HALFB]);

    cfl A3[2], B3[2], C3[2];
#pragma unroll
    for (int u = 0; u < 2; ++u) { A3[u] = mkc(0,0); B3[u] = mkc(0,0); C3[u] = mkc(0,0); }

#pragma unroll 1
    for (int i3 = 0; i3 < 3; ++i3) {
        cfl A2[2], B2[2], C2[2];
#pragma unroll
        for (int i2 = 0; i2 < 3; ++i2) {
            cfl v1[3][2];
#pragma unroll
            for (int i1 = 0; i1 < 3; ++i1) {
                cfl lv[3][2];
#pragma unroll
                for (int i0 = 0; i0 < 3; ++i0) {
                    int l = ((i3 * 3 + i2) * 3 + i1) * 3 + i0;   // 0..80 local
                    float4 lp = sL[l];
#pragma unroll
                    for (int u = 0; u < 2; ++u)
                        lv[i0][u] = mkc(lp.x + lp.z * xr[u], lp.y);
                }
                int g = (i3 * 3 + i2) * 3 + i1;                  // local 0..26
                nodeS<2>(sG + g * 12, xr, lv[0], lv[1], lv[2], v1[i1]);
            }
            cfl v2[2];
            nodeS<2>(sG + (27 + i3 * 3 + i2) * 12, xr, v1[0], v1[1], v1[2], v2);
#pragma unroll
            for (int u = 0; u < 2; ++u) {
                if (i2 == 0) A2[u] = v2[u];
                else if (i2 == 1) B2[u] = v2[u];
                else C2[u] = v2[u];
            }
        }
        cfl v3[2];
        nodeS<2>(sG + (36 + i3) * 12, xr, A2, B2, C2, v3);
#pragma unroll
        for (int u = 0; u < 2; ++u) { A3[u] = B3[u]; B3[u] = C3[u]; C3[u] = v3[u]; }
    }
    cfl v[2];
    nodeS<2>(sG + 39 * 12, xr, A3, B3, C3, v);
    d_v81[j * TT_BATCH + b0]            = make_float2(v[0].re, v[0].im);
    d_v81[j * TT_BATCH + b0 + TT_HALFB] = make_float2(v[1].re, v[1].im);
}

// ---------------------------------------------------------------------------
// stage B: fold 81 -> 1; gate bases 27@3240, 9@3267, 3@3276, root@3279
// rmode: 0 = interleaved (re,im); 1 = planar re then im; 2 = re only
// ---------------------------------------------------------------------------
__global__ void __launch_bounds__(256) stageB_kernel(const float* __restrict__ x,
                                                     float* __restrict__ out,
                                                     int rmode)
{
    int b = blockIdx.x * blockDim.x + threadIdx.x;
    float xr[1];
    xr[0] = __ldg(&x[b]);

    cfl A3[1], B3[1], C3[1];
    A3[0] = mkc(0,0); B3[0] = mkc(0,0); C3[0] = mkc(0,0);

#pragma unroll 1
    for (int i3 = 0; i3 < 3; ++i3) {
        cfl A2[1], B2[1], C2[1];
#pragma unroll
        for (int i2 = 0; i2 < 3; ++i2) {
            cfl v1[3][1];
#pragma unroll
            for (int i1 = 0; i1 < 3; ++i1) {
                int m = (i3 * 3 + i2) * 3 + i1;   // 27-level node 0..26
                float2 u0 = __ldg(&d_v81[(3 * m + 0) * TT_BATCH + b]);
                float2 u1 = __ldg(&d_v81[(3 * m + 1) * TT_BATCH + b]);
                float2 u2 = __ldg(&d_v81[(3 * m + 2) * TT_BATCH + b]);
                cfl c0[1] = { mkc(u0.x, u0.y) };
                cfl c1[1] = { mkc(u1.x, u1.y) };
                cfl c2[1] = { mkc(u2.x, u2.y) };
                nodeG<1>(d_gatePack + (3240 + m) * 12, xr, c0, c1, c2, v1[i1]);
            }
            cfl v2[1];
            nodeG<1>(d_gatePack + (3267 + i3 * 3 + i2) * 12, xr,
                     v1[0], v1[1], v1[2], v2);
            if (i2 == 0) A2[0] = v2[0]; else if (i2 == 1) B2[0] = v2[0]; else C2[0] = v2[0];
        }
        cfl v3[1];
        nodeG<1>(d_gatePack + (3276 + i3) * 12, xr, A2, B2, C2, v3);
        A3[0] = B3[0]; B3[0] = C3[0]; C3[0] = v3[0];
    }
    cfl r[1];
    nodeG<1>(d_gatePack + 3279 * 12, xr, A3, B3, C3, r);

    if (rmode == 0) {
        out[2 * b + 0] = r[0].re;
        out[2 * b + 1] = r[0].im;
    } else if (rmode == 1) {
        out[b]            = r[0].re;
        out[TT_BATCH + b] = r[0].im;
    } else {
        out[b] = r[0].re;
    }
}

// ---------------------------------------------------------------------------
extern "C" void kernel_launch(void* const* d_in, const int* in_sizes, int n_in,
                              void* d_out, int out_size)
{
    // size-based input resolution (dict order; first 13122 = leaf_logits)
    const float* x  = 0;
    const float* ll = 0;
    const float* lc = 0;
    const float* gl = 0;
    const float* gc = 0;
    int n13122 = 0;
    for (int i = 0; i < n_in; ++i) {
        const float* p = (const float*)d_in[i];
        int s = in_sizes[i];
        if      (s == 16384) x  = p;
        else if (s == 29520) gl = p;
        else if (s == 19680) gc = p;
        else if (s == 13122) { if (n13122++ == 0) ll = p; else lc = p; }
    }
    float* out = (float*)d_out;

    // ---- output layout selection from out_size (VALIDATED in R6 — do not change) ----
    int pstyle, leafBase, gateBase, rmode;
    if (out_size == 59026) {
        rmode = 2; pstyle = 1; leafBase = 16384; gateBase = 29506;   // real-part concat
    } else if (out_size == 75410) {
        rmode = 1; pstyle = 1; leafBase = 32768; gateBase = 45890;
    } else if (out_size == 118052) {
        rmode = 0; pstyle = 2; leafBase = 32768; gateBase = 32768 + 26244;
    } else if (out_size == 32768) {
        rmode = 1; pstyle = 0; leafBase = 0; gateBase = 0;
    } else if (out_size == 16384) {
        rmode = 2; pstyle = 0; leafBase = 0; gateBase = 0;
    } else {
        rmode = 0; pstyle = 0; leafBase = 0; gateBase = 0;
    }

    int prepThreads = TT_NINTERNAL * 3;
    prep_kernel<<<(prepThreads + 255) / 256, 256>>>(ll, lc, gl, gc, out,
                                                    pstyle, leafBase, gateBase);

    dim3 gridA(TT_HALFB / 256, 81);      // U=2 batch elements per thread
    stageA_kernel<<<gridA, 256>>>(x);

    stageB_kernel<<<TT_BATCH / 256, 256>>>(x, out, rmode);
}

// round 14
// speedup vs baseline: 1.4720x; 1.0176x over previous
#include <cuda_runtime.h>
#include <math.h>

// TernaryTree1D: depth-8 ternary tree, BATCH=16384, 6561 leaves, 3280 internal nodes.
// R6: output layout locked. R7: premultiplied packs + fast recip (116.8us).
// R9: branchless clamp + smem constants (96.0us).
// R10/R13: stageA with Blackwell packed f32x2 (mul/add/fma.rn.f32x2) — one
// instruction computes both batch lanes; constants splatted in smem at preload.
// (R12 bench was an infra failure — identical resubmission.)

#define TT_BATCH 16384
#define TT_HALFB 8192
#define TT_NLEAVES 6561
#define TT_NINTERNAL 3280
#define TT_EPS 1e-6f
#define TT_CAP 1000000.0f
#define TT_CAPSQ 1e12f

typedef unsigned long long u64;

struct cfl { float re, im; };
__device__ __forceinline__ cfl mkc(float r, float i) { cfl v; v.re = r; v.im = i; return v; }
struct c2 { u64 re, im; };          // complex pair: two batch lanes packed f32x2

// ---- f32x2 primitives (sm_100a PTX ISA 8.6) ----
__device__ __forceinline__ u64 pk2(float lo, float hi) {
    u64 r;
    asm("mov.b64 %0, {%1, %2};" : "=l"(r) : "r"(__float_as_uint(lo)), "r"(__float_as_uint(hi)));
    return r;
}
__device__ __forceinline__ void upk2(u64 v, float& lo, float& hi) {
    unsigned int a, b;
    asm("mov.b64 {%0, %1}, %2;" : "=r"(a), "=r"(b) : "l"(v));
    lo = __uint_as_float(a); hi = __uint_as_float(b);
}
__device__ __forceinline__ u64 f2mul(u64 a, u64 b) {
    u64 d; asm("mul.rn.f32x2 %0, %1, %2;" : "=l"(d) : "l"(a), "l"(b)); return d;
}
__device__ __forceinline__ u64 f2add(u64 a, u64 b) {
    u64 d; asm("add.rn.f32x2 %0, %1, %2;" : "=l"(d) : "l"(a), "l"(b)); return d;
}
__device__ __forceinline__ u64 f2fma(u64 a, u64 b, u64 c) {
    u64 d; asm("fma.rn.f32x2 %0, %1, %2, %3;" : "=l"(d) : "l"(a), "l"(b), "l"(c)); return d;
}
__device__ __forceinline__ u64 f2neg(u64 a) { return a ^ 0x8000000080000000ULL; }
__device__ __forceinline__ float frcp(float x) {
    float r; asm("rcp.approx.f32 %0, %1;" : "=f"(r) : "f"(x)); return r;
}

#define EPS2_BITS 0x358637BD358637BDULL   // (1e-6f, 1e-6f)

// ---- scratch (device globals, ~10.8 MB total — mem-guard-safe) ----
__device__ float4 d_leafPack[TT_NLEAVES];            // (w0*cr, w0*ci, w1, pad)
__device__ float  d_gatePack[TT_NINTERNAL * 12];     // 3 rows of (p0*cr, p0*ci, p1, p2)
__device__ float2 d_v81[81 * TT_BATCH];              // 81-level values, [j][b]

// ---------------------------------------------------------------------------
// prep: softmax leaf + gate logits; premultiplied packs; probs -> out.
// ---------------------------------------------------------------------------
__global__ void prep_kernel(const float* __restrict__ leaf_logits,
                            const float* __restrict__ leaf_c,
                            const float* __restrict__ gate_logits,
                            const float* __restrict__ gate_c,
                            float* __restrict__ out,
                            int pstyle, int leafBase, int gateBase)
{
    int idx = blockIdx.x * blockDim.x + threadIdx.x;

    if (idx < TT_NLEAVES) {
        float l0 = leaf_logits[idx * 2 + 0];
        float l1 = leaf_logits[idx * 2 + 1];
        float m  = fmaxf(l0, l1);
        float e0 = expf(l0 - m), e1 = expf(l1 - m);
        float s  = e0 + e1;
        float w0 = e0 / s, w1 = e1 / s;
        if (pstyle == 1) {
            out[leafBase + idx * 2 + 0] = w0;
            out[leafBase + idx * 2 + 1] = w1;
        } else if (pstyle == 2) {
            out[leafBase + idx * 4 + 0] = w0; out[leafBase + idx * 4 + 1] = 0.0f;
            out[leafBase + idx * 4 + 2] = w1; out[leafBase + idx * 4 + 3] = 0.0f;
        }
        float cr = leaf_c[idx * 2 + 0];
        float ci = leaf_c[idx * 2 + 1];
        d_leafPack[idx] = make_float4(w0 * cr, w0 * ci, w1, 0.0f);
    }

    if (idx < TT_NINTERNAL * 3) {
        int n = idx / 3;
        int i = idx % 3;
        float g0 = gate_logits[n * 9 + i * 3 + 0];
        float g1 = gate_logits[n * 9 + i * 3 + 1];
        float g2 = gate_logits[n * 9 + i * 3 + 2];
        float m  = fmaxf(g0, fmaxf(g1, g2));
        float e0 = expf(g0 - m), e1 = expf(g1 - m), e2 = expf(g2 - m);
        float s  = e0 + e1 + e2;
        float p0 = e0 / s, p1 = e1 / s, p2 = e2 / s;
        int k = n * 9 + i * 3;
        if (pstyle == 1) {
            out[gateBase + k + 0] = p0;
            out[gateBase + k + 1] = p1;
            out[gateBase + k + 2] = p2;
        } else if (pstyle == 2) {
            int base = gateBase + 2 * k;
            out[base + 0] = p0; out[base + 1] = 0.0f;
            out[base + 2] = p1; out[base + 3] = 0.0f;
            out[base + 4] = p2; out[base + 5] = 0.0f;
        }
        float cr = gate_c[n * 6 + i * 2 + 0];
        float ci = gate_c[n * 6 + i * 2 + 1];
        float* g = d_gatePack + n * 12 + i * 4;
        g[0] = p0 * cr;
        g[1] = p0 * ci;
        g[2] = p1;
        g[3] = p2;
    }
}

// ---------------------------------------------------------------------------
// packed node: constants pre-splatted in smem as u64 pairs, data = 2 batch lanes.
// g layout per node (ulonglong2[6]): (e0,f0)(p10,p20)(e1,f1)(p11,p21)(e2,f2)(p12,p22)
// ---------------------------------------------------------------------------
__device__ __forceinline__ c2 nodeP(const ulonglong2* g, u64 x01,
                                    c2 va, c2 vb, c2 vc)
{
    ulonglong2 gA = g[0], gB = g[1];
    ulonglong2 gC = g[2], gD = g[3];
    ulonglong2 gE = g[4], gF = g[5];

    u64 ar = f2fma(gB.y, va.re, f2fma(gB.x, x01, gA.x));
    u64 ai = f2fma(gB.y, va.im, gA.y);
    u64 br = f2fma(gD.y, vb.re, f2fma(gD.x, x01, gC.x));
    u64 bi = f2fma(gD.y, vb.im, gC.y);
    u64 cr = f2fma(gF.y, vc.re, f2fma(gF.x, x01, gE.x));
    u64 ci = f2fma(gF.y, vc.im, gE.y);

    u64 den = f2add(f2fma(ci, ci, f2mul(cr, cr)), EPS2_BITS);
    u64 abr = f2fma(ar, br, f2neg(f2mul(ai, bi)));
    u64 abi = f2fma(ai, br, f2mul(ar, bi));
    u64 nr  = f2fma(abi, ci, f2mul(abr, cr));
    u64 ni  = f2fma(abi, cr, f2neg(f2mul(abr, ci)));

    float dlo, dhi; upk2(den, dlo, dhi);
    u64 inv = pk2(frcp(dlo), frcp(dhi));
    u64 orr = f2mul(nr, inv);
    u64 oi  = f2mul(ni, inv);

    u64 m2 = f2fma(oi, oi, f2mul(orr, orr));
    float mlo, mhi; upk2(m2, mlo, mhi);
    if (fmaxf(mlo, mhi) > TT_CAPSQ) {       // rare: exact skip when not clamped
        float slo = fminf(1.0f, TT_CAP * rsqrtf(mlo));
        float shi = fminf(1.0f, TT_CAP * rsqrtf(mhi));
        u64 s = pk2(slo, shi);
        orr = f2mul(orr, s);
        oi  = f2mul(oi, s);
    }
    c2 o; o.re = orr; o.im = oi; return o;
}

// ---------------------------------------------------------------------------
// stage A: thread folds one depth-4 subtree for 2 batch elements (packed f32x2).
// smem: 40 gates x 12 splatted consts + 81 leaves x 4 splatted consts.
// ---------------------------------------------------------------------------
__global__ void __launch_bounds__(256) stageA_kernel(const float* __restrict__ x)
{
    __shared__ __align__(16) u64 sG2[40 * 12];
    __shared__ __align__(16) u64 sL2[81 * 4];

    int j = blockIdx.y;                               // subtree 0..80
    int t = threadIdx.x;

    int g2187Base = j * 27;
    int g729Base  = 2187 + j * 9;
    int g243Base  = 2916 + j * 3;

    // cooperative preload with splatting
    for (int q = t; q < 40 * 12; q += 256) {
        int lg = q / 12, r = q - lg * 12;
        int gg = (lg < 27) ? (g2187Base + lg)
               : (lg < 36) ? (g729Base + (lg - 27))
               : (lg < 39) ? (g243Base + (lg - 36))
                           : (3159 + j);
        unsigned int b = __float_as_uint(d_gatePack[gg * 12 + r]);
        sG2[q] = ((u64)b << 32) | b;
    }
    for (int q = t; q < 81 * 4; q += 256) {
        int l = q >> 2, c = q & 3;
        const float* lp = (const float*)&d_leafPack[j * 81 + l];
        unsigned int b = __float_as_uint(lp[c]);
        sL2[q] = ((u64)b << 32) | b;
    }
    __syncthreads();

    int b0 = blockIdx.x * blockDim.x + t;             // 0..8191
    u64 x01 = pk2(__ldg(&x[b0]), __ldg(&x[b0 + TT_HALFB]));

    c2 A3, B3, C3;
    A3.re = A3.im = B3.re = B3.im = C3.re = C3.im = 0ULL;

#pragma unroll 1
    for (int i3 = 0; i3 < 3; ++i3) {
        c2 A2, B2, C2;
#pragma unroll
        for (int i2 = 0; i2 < 3; ++i2) {
            c2 v1[3];
#pragma unroll
            for (int i1 = 0; i1 < 3; ++i1) {
                c2 lv[3];
#pragma unroll
                for (int i0 = 0; i0 < 3; ++i0) {
                    int l = ((i3 * 3 + i2) * 3 + i1) * 3 + i0;   // 0..80 local
                    const u64* lp = sL2 + l * 4;
                    lv[i0].re = f2fma(lp[2], x01, lp[0]);        // w0*cr + w1*x
                    lv[i0].im = lp[1];                           // w0*ci
                }
                int g = (i3 * 3 + i2) * 3 + i1;                  // local 0..26
                v1[i1] = nodeP((const ulonglong2*)(sG2 + g * 12), x01,
                               lv[0], lv[1], lv[2]);
            }
            c2 v2 = nodeP((const ulonglong2*)(sG2 + (27 + i3 * 3 + i2) * 12), x01,
                          v1[0], v1[1], v1[2]);
            if (i2 == 0) A2 = v2; else if (i2 == 1) B2 = v2; else C2 = v2;
        }
        c2 v3 = nodeP((const ulonglong2*)(sG2 + (36 + i3) * 12), x01, A2, B2, C2);
        A3 = B3; B3 = C3; C3 = v3;
    }
    c2 v = nodeP((const ulonglong2*)(sG2 + 39 * 12), x01, A3, B3, C3);

    float r0, r1, i0f, i1f;
    upk2(v.re, r0, r1);
    upk2(v.im, i0f, i1f);
    d_v81[j * TT_BATCH + b0]            = make_float2(r0, i0f);
    d_v81[j * TT_BATCH + b0 + TT_HALFB] = make_float2(r1, i1f);
}

// ---------------------------------------------------------------------------
// scalar node (stageB): same math as R9.
// ---------------------------------------------------------------------------
__device__ __forceinline__ cfl nodeG(const float* __restrict__ gp, float xr,
                                     cfl va, cfl vb, cfl vc)
{
    const float4* g4 = reinterpret_cast<const float4*>(gp);
    float4 r0 = __ldg(g4 + 0);
    float4 r1 = __ldg(g4 + 1);
    float4 r2 = __ldg(g4 + 2);
    float ar = r0.x + r0.z * xr + r0.w * va.re;
    float ai = r0.y + r0.w * va.im;
    float br = r1.x + r1.z * xr + r1.w * vb.re;
    float bi = r1.y + r1.w * vb.im;
    float cr = r2.x + r2.z * xr + r2.w * vc.re;
    float ci = r2.y + r2.w * vc.im;

    float den = cr * cr + ci * ci + TT_EPS;
    float abr = ar * br - ai * bi;
    float abi = ar * bi + ai * br;
    float nr  = abr * cr + abi * ci;
    float ni  = abi * cr - abr * ci;
    float inv = __fdividef(1.0f, den);
    float orr = nr * inv;
    float oi  = ni * inv;
    float m2  = orr * orr + oi * oi;
    float s   = fminf(1.0f, TT_CAP * rsqrtf(m2));
    return mkc(orr * s, oi * s);
}

// ---------------------------------------------------------------------------
// stage B: fold 81 -> 1; gate bases 27@3240, 9@3267, 3@3276, root@3279
// rmode: 0 = interleaved (re,im); 1 = planar re then im; 2 = re only
// ---------------------------------------------------------------------------
__global__ void __launch_bounds__(256) stageB_kernel(const float* __restrict__ x,
                                                     float* __restrict__ out,
                                                     int rmode)
{
    int b = blockIdx.x * blockDim.x + threadIdx.x;
    float xr = __ldg(&x[b]);

    cfl A3 = mkc(0,0), B3 = mkc(0,0), C3 = mkc(0,0);

#pragma unroll 1
    for (int i3 = 0; i3 < 3; ++i3) {
        cfl A2 = mkc(0,0), B2 = mkc(0,0), C2 = mkc(0,0);
#pragma unroll
        for (int i2 = 0; i2 < 3; ++i2) {
            cfl v1[3];
#pragma unroll
            for (int i1 = 0; i1 < 3; ++i1) {
                int m = (i3 * 3 + i2) * 3 + i1;   // 27-level node 0..26
                float2 u0 = __ldg(&d_v81[(3 * m + 0) * TT_BATCH + b]);
                float2 u1 = __ldg(&d_v81[(3 * m + 1) * TT_BATCH + b]);
                float2 u2 = __ldg(&d_v81[(3 * m + 2) * TT_BATCH + b]);
                v1[i1] = nodeG(d_gatePack + (3240 + m) * 12, xr,
                               mkc(u0.x, u0.y), mkc(u1.x, u1.y), mkc(u2.x, u2.y));
            }
            cfl v2 = nodeG(d_gatePack + (3267 + i3 * 3 + i2) * 12, xr,
                           v1[0], v1[1], v1[2]);
            if (i2 == 0) A2 = v2; else if (i2 == 1) B2 = v2; else C2 = v2;
        }
        cfl v3 = nodeG(d_gatePack + (3276 + i3) * 12, xr, A2, B2, C2);
        A3 = B3; B3 = C3; C3 = v3;
    }
    cfl r = nodeG(d_gatePack + 3279 * 12, xr, A3, B3, C3);

    if (rmode == 0) {
        out[2 * b + 0] = r.re;
        out[2 * b + 1] = r.im;
    } else if (rmode == 1) {
        out[b]            = r.re;
        out[TT_BATCH + b] = r.im;
    } else {
        out[b] = r.re;
    }
}

// ---------------------------------------------------------------------------
extern "C" void kernel_launch(void* const* d_in, const int* in_sizes, int n_in,
                              void* d_out, int out_size)
{
    // size-based input resolution (dict order; first 13122 = leaf_logits)
    const float* x  = 0;
    const float* ll = 0;
    const float* lc = 0;
    const float* gl = 0;
    const float* gc = 0;
    int n13122 = 0;
    for (int i = 0; i < n_in; ++i) {
        const float* p = (const float*)d_in[i];
        int s = in_sizes[i];
        if      (s == 16384) x  = p;
        else if (s == 29520) gl = p;
        else if (s == 19680) gc = p;
        else if (s == 13122) { if (n13122++ == 0) ll = p; else lc = p; }
    }
    float* out = (float*)d_out;

    // ---- output layout selection from out_size (VALIDATED in R6 — do not change) ----
    int pstyle, leafBase, gateBase, rmode;
    if (out_size == 59026) {
        rmode = 2; pstyle = 1; leafBase = 16384; gateBase = 29506;   // real-part concat
    } else if (out_size == 75410) {
        rmode = 1; pstyle = 1; leafBase = 32768; gateBase = 45890;
    } else if (out_size == 118052) {
        rmode = 0; pstyle = 2; leafBase = 32768; gateBase = 32768 + 26244;
    } else if (out_size == 32768) {
        rmode = 1; pstyle = 0; leafBase = 0; gateBase = 0;
    } else if (out_size == 16384) {
        rmode = 2; pstyle = 0; leafBase = 0; gateBase = 0;
    } else {
        rmode = 0; pstyle = 0; leafBase = 0; gateBase = 0;
    }

    int prepThreads = TT_NINTERNAL * 3;
    prep_kernel<<<(prepThreads + 255) / 256, 256>>>(ll, lc, gl, gc, out,
                                                    pstyle, leafBase, gateBase);

    dim3 gridA(TT_HALFB / 256, 81);      // U=2 packed batch elements per thread
    stageA_kernel<<<gridA, 256>>>(x);

    stageB_kernel<<<TT_BATCH / 256, 256>>>(x, out, rmode);
}

// round 15
// speedup vs baseline: 1.5780x; 1.0720x over previous
#include <cuda_runtime.h>
#include <math.h>

// TernaryTree1D: depth-8 ternary tree, BATCH=16384, 6561 leaves, 3280 internal nodes.
// R6: output layout locked. R7: premultiplied packs + fast recip. R9: smem consts +
// branchless clamp (96.0us). R13: packed f32x2 lanes (94.4us).
// R15: prep kernel fused into stageA/stageB preload phases (2-kernel graph).

#define TT_BATCH 16384
#define TT_HALFB 8192
#define TT_NLEAVES 6561
#define TT_NINTERNAL 3280
#define TT_EPS 1e-6f
#define TT_CAP 1000000.0f
#define TT_CAPSQ 1e12f

typedef unsigned long long u64;

struct cfl { float re, im; };
__device__ __forceinline__ cfl mkc(float r, float i) { cfl v; v.re = r; v.im = i; return v; }
struct c2 { u64 re, im; };          // complex pair: two batch lanes packed f32x2

// ---- f32x2 primitives ----
__device__ __forceinline__ u64 pk2(float lo, float hi) {
    u64 r;
    asm("mov.b64 %0, {%1, %2};" : "=l"(r) : "r"(__float_as_uint(lo)), "r"(__float_as_uint(hi)));
    return r;
}
__device__ __forceinline__ void upk2(u64 v, float& lo, float& hi) {
    unsigned int a, b;
    asm("mov.b64 {%0, %1}, %2;" : "=r"(a), "=r"(b) : "l"(v));
    lo = __uint_as_float(a); hi = __uint_as_float(b);
}
__device__ __forceinline__ u64 f2mul(u64 a, u64 b) {
    u64 d; asm("mul.rn.f32x2 %0, %1, %2;" : "=l"(d) : "l"(a), "l"(b)); return d;
}
__device__ __forceinline__ u64 f2add(u64 a, u64 b) {
    u64 d; asm("add.rn.f32x2 %0, %1, %2;" : "=l"(d) : "l"(a), "l"(b)); return d;
}
__device__ __forceinline__ u64 f2fma(u64 a, u64 b, u64 c) {
    u64 d; asm("fma.rn.f32x2 %0, %1, %2, %3;" : "=l"(d) : "l"(a), "l"(b), "l"(c)); return d;
}
__device__ __forceinline__ u64 f2neg(u64 a) { return a ^ 0x8000000080000000ULL; }
__device__ __forceinline__ float frcp(float x) {
    float r; asm("rcp.approx.f32 %0, %1;" : "=f"(r) : "f"(x)); return r;
}
__device__ __forceinline__ u64 splat(float v) {
    unsigned int b = __float_as_uint(v);
    return ((u64)b << 32) | b;
}

#define EPS2_BITS 0x358637BD358637BDULL   // (1e-6f, 1e-6f)

// ---- scratch (device global, ~10.5 MB — mem-guard-safe) ----
__device__ float2 d_v81[81 * TT_BATCH];              // 81-level values, [j][b]

// ---------------------------------------------------------------------------
// softmax helpers (identical arithmetic to the validated prep kernel)
// ---------------------------------------------------------------------------
__device__ __forceinline__ void softmax3(float g0, float g1, float g2,
                                         float& p0, float& p1, float& p2)
{
    float m  = fmaxf(g0, fmaxf(g1, g2));
    float e0 = expf(g0 - m), e1 = expf(g1 - m), e2 = expf(g2 - m);
    float s  = e0 + e1 + e2;
    p0 = e0 / s; p1 = e1 / s; p2 = e2 / s;
}

// ---------------------------------------------------------------------------
// packed node: constants pre-splatted in smem, data = 2 batch lanes (f32x2).
// g layout per node (ulonglong2[6]): (e0,f0)(p10,p20)(e1,f1)(p11,p21)(e2,f2)(p12,p22)
// ---------------------------------------------------------------------------
__device__ __forceinline__ c2 nodeP(const ulonglong2* g, u64 x01,
                                    c2 va, c2 vb, c2 vc)
{
    ulonglong2 gA = g[0], gB = g[1];
    ulonglong2 gC = g[2], gD = g[3];
    ulonglong2 gE = g[4], gF = g[5];

    u64 ar = f2fma(gB.y, va.re, f2fma(gB.x, x01, gA.x));
    u64 ai = f2fma(gB.y, va.im, gA.y);
    u64 br = f2fma(gD.y, vb.re, f2fma(gD.x, x01, gC.x));
    u64 bi = f2fma(gD.y, vb.im, gC.y);
    u64 cr = f2fma(gF.y, vc.re, f2fma(gF.x, x01, gE.x));
    u64 ci = f2fma(gF.y, vc.im, gE.y);

    u64 den = f2add(f2fma(ci, ci, f2mul(cr, cr)), EPS2_BITS);
    u64 abr = f2fma(ar, br, f2neg(f2mul(ai, bi)));
    u64 abi = f2fma(ai, br, f2mul(ar, bi));
    u64 nr  = f2fma(abi, ci, f2mul(abr, cr));
    u64 ni  = f2fma(abi, cr, f2neg(f2mul(abr, ci)));

    float dlo, dhi; upk2(den, dlo, dhi);
    u64 inv = pk2(frcp(dlo), frcp(dhi));
    u64 orr = f2mul(nr, inv);
    u64 oi  = f2mul(ni, inv);

    u64 m2 = f2fma(oi, oi, f2mul(orr, orr));
    float mlo, mhi; upk2(m2, mlo, mhi);
    if (fmaxf(mlo, mhi) > TT_CAPSQ) {       // rare: exact skip when not clamped
        float slo = fminf(1.0f, TT_CAP * rsqrtf(mlo));
        float shi = fminf(1.0f, TT_CAP * rsqrtf(mhi));
        u64 s = pk2(slo, shi);
        orr = f2mul(orr, s);
        oi  = f2mul(oi, s);
    }
    c2 o; o.re = orr; o.im = oi; return o;
}

// ---------------------------------------------------------------------------
// stage A: thread folds one depth-4 subtree for 2 batch elements (packed).
// Preload phase computes this block's softmax packs directly from raw inputs
// (prep kernel fused away); blockIdx.x==0 also writes prob outputs for its j.
// ---------------------------------------------------------------------------
__global__ void __launch_bounds__(256) stageA_kernel(
    const float* __restrict__ x,
    const float* __restrict__ leaf_logits,
    const float* __restrict__ leaf_c,
    const float* __restrict__ gate_logits,
    const float* __restrict__ gate_c,
    float* __restrict__ out,
    int pstyle, int leafBaseO, int gateBaseO)
{
    __shared__ __align__(16) u64 sG2[40 * 12];
    __shared__ __align__(16) u64 sL2[81 * 4];

    int j = blockIdx.y;                               // subtree 0..80
    int t = threadIdx.x;
    bool writer = (blockIdx.x == 0) && (pstyle != 0);

    // ---- fused preload: softmax + premultiply + splat (one task per thread) ----
    if (t < 120) {                                    // gate rows: 40 gates x 3
        int lg = t / 3, i = t - lg * 3;
        int gg = (lg < 27) ? (j * 27 + lg)
               : (lg < 36) ? (2187 + j * 9 + (lg - 27))
               : (lg < 39) ? (2916 + j * 3 + (lg - 36))
                           : (3159 + j);
        float p0, p1, p2;
        softmax3(gate_logits[gg * 9 + i * 3 + 0],
                 gate_logits[gg * 9 + i * 3 + 1],
                 gate_logits[gg * 9 + i * 3 + 2], p0, p1, p2);
        float cr = gate_c[gg * 6 + i * 2 + 0];
        float ci = gate_c[gg * 6 + i * 2 + 1];
        u64* g = sG2 + lg * 12 + i * 4;
        g[0] = splat(p0 * cr);
        g[1] = splat(p0 * ci);
        g[2] = splat(p1);
        g[3] = splat(p2);
        if (writer) {
            int k = gg * 9 + i * 3;
            if (pstyle == 1) {
                out[gateBaseO + k + 0] = p0;
                out[gateBaseO + k + 1] = p1;
                out[gateBaseO + k + 2] = p2;
            } else {
                int base = gateBaseO + 2 * k;
                out[base + 0] = p0; out[base + 1] = 0.0f;
                out[base + 2] = p1; out[base + 3] = 0.0f;
                out[base + 4] = p2; out[base + 5] = 0.0f;
            }
        }
    } else if (t < 201) {                             // leaves: 81
        int l = t - 120;
        int gidx = j * 81 + l;
        float l0 = leaf_logits[gidx * 2 + 0];
        float l1 = leaf_logits[gidx * 2 + 1];
        float m  = fmaxf(l0, l1);
        float e0 = expf(l0 - m), e1 = expf(l1 - m);
        float s  = e0 + e1;
        float w0 = e0 / s, w1 = e1 / s;
        float cr = leaf_c[gidx * 2 + 0];
        float ci = leaf_c[gidx * 2 + 1];
        u64* lp = sL2 + l * 4;
        lp[0] = splat(w0 * cr);
        lp[1] = splat(w0 * ci);
        lp[2] = splat(w1);
        lp[3] = 0ULL;
        if (writer) {
            if (pstyle == 1) {
                out[leafBaseO + gidx * 2 + 0] = w0;
                out[leafBaseO + gidx * 2 + 1] = w1;
            } else {
                out[leafBaseO + gidx * 4 + 0] = w0; out[leafBaseO + gidx * 4 + 1] = 0.0f;
                out[leafBaseO + gidx * 4 + 2] = w1; out[leafBaseO + gidx * 4 + 3] = 0.0f;
            }
        }
    }
    __syncthreads();

    int b0 = blockIdx.x * blockDim.x + t;             // 0..8191
    u64 x01 = pk2(__ldg(&x[b0]), __ldg(&x[b0 + TT_HALFB]));

    c2 A3, B3, C3;
    A3.re = A3.im = B3.re = B3.im = C3.re = C3.im = 0ULL;

#pragma unroll 1
    for (int i3 = 0; i3 < 3; ++i3) {
        c2 A2, B2, C2;
#pragma unroll
        for (int i2 = 0; i2 < 3; ++i2) {
            c2 v1[3];
#pragma unroll
            for (int i1 = 0; i1 < 3; ++i1) {
                c2 lv[3];
#pragma unroll
                for (int i0 = 0; i0 < 3; ++i0) {
                    int l = ((i3 * 3 + i2) * 3 + i1) * 3 + i0;   // 0..80 local
                    const u64* lp = sL2 + l * 4;
                    lv[i0].re = f2fma(lp[2], x01, lp[0]);        // w0*cr + w1*x
                    lv[i0].im = lp[1];                           // w0*ci
                }
                int g = (i3 * 3 + i2) * 3 + i1;                  // local 0..26
                v1[i1] = nodeP((const ulonglong2*)(sG2 + g * 12), x01,
                               lv[0], lv[1], lv[2]);
            }
            c2 v2 = nodeP((const ulonglong2*)(sG2 + (27 + i3 * 3 + i2) * 12), x01,
                          v1[0], v1[1], v1[2]);
            if (i2 == 0) A2 = v2; else if (i2 == 1) B2 = v2; else C2 = v2;
        }
        c2 v3 = nodeP((const ulonglong2*)(sG2 + (36 + i3) * 12), x01, A2, B2, C2);
        A3 = B3; B3 = C3; C3 = v3;
    }
    c2 v = nodeP((const ulonglong2*)(sG2 + 39 * 12), x01, A3, B3, C3);

    float r0, r1, i0f, i1f;
    upk2(v.re, r0, r1);
    upk2(v.im, i0f, i1f);
    d_v81[j * TT_BATCH + b0]            = make_float2(r0, i0f);
    d_v81[j * TT_BATCH + b0 + TT_HALFB] = make_float2(r1, i1f);
}

// ---------------------------------------------------------------------------
// scalar node reading smem constants (stageB)
// ---------------------------------------------------------------------------
__device__ __forceinline__ cfl nodeS(const float* gp, float xr,
                                     cfl va, cfl vb, cfl vc)
{
    const float4* g4 = reinterpret_cast<const float4*>(gp);
    float4 r0 = g4[0];
    float4 r1 = g4[1];
    float4 r2 = g4[2];
    float ar = r0.x + r0.z * xr + r0.w * va.re;
    float ai = r0.y + r0.w * va.im;
    float br = r1.x + r1.z * xr + r1.w * vb.re;
    float bi = r1.y + r1.w * vb.im;
    float cr = r2.x + r2.z * xr + r2.w * vc.re;
    float ci = r2.y + r2.w * vc.im;

    float den = cr * cr + ci * ci + TT_EPS;
    float abr = ar * br - ai * bi;
    float abi = ar * bi + ai * br;
    float nr  = abr * cr + abi * ci;
    float ni  = abi * cr - abr * ci;
    float inv = __fdividef(1.0f, den);
    float orr = nr * inv;
    float oi  = ni * inv;
    float m2  = orr * orr + oi * oi;
    float s   = fminf(1.0f, TT_CAP * rsqrtf(m2));
    return mkc(orr * s, oi * s);
}

// ---------------------------------------------------------------------------
// stage B: fold 81 -> 1; local gates 0..39 = global 3240..3279
// (27-level @3240, 9 @3267, 3 @3276, root @3279 — local layout mirrors stageA)
// rmode: 0 = interleaved (re,im); 1 = planar re then im; 2 = re only
// ---------------------------------------------------------------------------
__global__ void __launch_bounds__(256) stageB_kernel(
    const float* __restrict__ x,
    const float* __restrict__ gate_logits,
    const float* __restrict__ gate_c,
    float* __restrict__ out,
    int rmode, int pstyle, int gateBaseO)
{
    __shared__ __align__(16) float sGB[40 * 12];

    int t = threadIdx.x;
    if (t < 120) {                                    // 40 gates x 3 rows
        int lg = t / 3, i = t - lg * 3;
        int gg = 3240 + lg;
        float p0, p1, p2;
        softmax3(gate_logits[gg * 9 + i * 3 + 0],
                 gate_logits[gg * 9 + i * 3 + 1],
                 gate_logits[gg * 9 + i * 3 + 2], p0, p1, p2);
        float cr = gate_c[gg * 6 + i * 2 + 0];
        float ci = gate_c[gg * 6 + i * 2 + 1];
        float* g = sGB + lg * 12 + i * 4;
        g[0] = p0 * cr;
        g[1] = p0 * ci;
        g[2] = p1;
        g[3] = p2;
        if (blockIdx.x == 0 && pstyle != 0) {
            int k = gg * 9 + i * 3;
            if (pstyle == 1) {
                out[gateBaseO + k + 0] = p0;
                out[gateBaseO + k + 1] = p1;
                out[gateBaseO + k + 2] = p2;
            } else {
                int base = gateBaseO + 2 * k;
                out[base + 0] = p0; out[base + 1] = 0.0f;
                out[base + 2] = p1; out[base + 3] = 0.0f;
                out[base + 4] = p2; out[base + 5] = 0.0f;
            }
        }
    }
    __syncthreads();

    int b = blockIdx.x * blockDim.x + t;
    float xr = __ldg(&x[b]);

    cfl A3 = mkc(0,0), B3 = mkc(0,0), C3 = mkc(0,0);

#pragma unroll 1
    for (int i3 = 0; i3 < 3; ++i3) {
        cfl A2 = mkc(0,0), B2 = mkc(0,0), C2 = mkc(0,0);
#pragma unroll
        for (int i2 = 0; i2 < 3; ++i2) {
            cfl v1[3];
#pragma unroll
            for (int i1 = 0; i1 < 3; ++i1) {
                int m = (i3 * 3 + i2) * 3 + i1;   // 27-level node 0..26
                float2 u0 = __ldg(&d_v81[(3 * m + 0) * TT_BATCH + b]);
                float2 u1 = __ldg(&d_v81[(3 * m + 1) * TT_BATCH + b]);
                float2 u2 = __ldg(&d_v81[(3 * m + 2) * TT_BATCH + b]);
                v1[i1] = nodeS(sGB + m * 12, xr,
                               mkc(u0.x, u0.y), mkc(u1.x, u1.y), mkc(u2.x, u2.y));
            }
            cfl v2 = nodeS(sGB + (27 + i3 * 3 + i2) * 12, xr, v1[0], v1[1], v1[2]);
            if (i2 == 0) A2 = v2; else if (i2 == 1) B2 = v2; else C2 = v2;
        }
        cfl v3 = nodeS(sGB + (36 + i3) * 12, xr, A2, B2, C2);
        A3 = B3; B3 = C3; C3 = v3;
    }
    cfl r = nodeS(sGB + 39 * 12, xr, A3, B3, C3);

    if (rmode == 0) {
        out[2 * b + 0] = r.re;
        out[2 * b + 1] = r.im;
    } else if (rmode == 1) {
        out[b]            = r.re;
        out[TT_BATCH + b] = r.im;
    } else {
        out[b] = r.re;
    }
}

// ---------------------------------------------------------------------------
extern "C" void kernel_launch(void* const* d_in, const int* in_sizes, int n_in,
                              void* d_out, int out_size)
{
    // size-based input resolution (dict order; first 13122 = leaf_logits)
    const float* x  = 0;
    const float* ll = 0;
    const float* lc = 0;
    const float* gl = 0;
    const float* gc = 0;
    int n13122 = 0;
    for (int i = 0; i < n_in; ++i) {
        const float* p = (const float*)d_in[i];
        int s = in_sizes[i];
        if      (s == 16384) x  = p;
        else if (s == 29520) gl = p;
        else if (s == 19680) gc = p;
        else if (s == 13122) { if (n13122++ == 0) ll = p; else lc = p; }
    }
    float* out = (float*)d_out;

    // ---- output layout selection from out_size (VALIDATED in R6 — do not change) ----
    int pstyle, leafBase, gateBase, rmode;
    if (out_size == 59026) {
        rmode = 2; pstyle = 1; leafBase = 16384; gateBase = 29506;   // real-part concat
    } else if (out_size == 75410) {
        rmode = 1; pstyle = 1; leafBase = 32768; gateBase = 45890;
    } else if (out_size == 118052) {
        rmode = 0; pstyle = 2; leafBase = 32768; gateBase = 32768 + 26244;
    } else if (out_size == 32768) {
        rmode = 1; pstyle = 0; leafBase = 0; gateBase = 0;
    } else if (out_size == 16384) {
        rmode = 2; pstyle = 0; leafBase = 0; gateBase = 0;
    } else {
        rmode = 0; pstyle = 0; leafBase = 0; gateBase = 0;
    }

    dim3 gridA(TT_HALFB / 256, 81);      // U=2 packed batch elements per thread
    stageA_kernel<<<gridA, 256>>>(x, ll, lc, gl, gc, out, pstyle, leafBase, gateBase);

    stageB_kernel<<<TT_BATCH / 256, 256>>>(x, gl, gc, out, rmode, pstyle, gateBase);
}